// round 17
// baseline (speedup 1.0000x reference)
#include <cuda_runtime.h>
#include <cstdint>

#define NN 50000
#define EE 800000
#define BDIM 64          // NBASES*FH
#define CWDIM 32         // NHEADS*NBASES
#define NBLK 196         // ceil(NN/256)

// ------------- scratch (device globals; referenced ONLY in device code) -----
__device__ float g_dis[NN];
__device__ int2  g_edge[EE];         // (row, col) per edge
__device__ int   g_cnt[NN];
__device__ int   g_off[NN];
__device__ int   g_cur[NN];
__device__ int   g_csr[EE];          // row ids grouped by col
__device__ int   g_total;
__device__ __align__(16) float g_sb [NN * BDIM];   // dis-scaled bases
__device__ __align__(16) float g_cw [NN * CWDIM];  // combination weights
__device__ __align__(16) float g_h1 [NN * 128];
__device__ float2 g_pre0[NN];
__device__ float2 g_pre1[NN];
__device__ int   g_is64;

// ------------- init: zero counters + dtype detect (single warp, ballot) -----
__global__ void k_init(const unsigned int* __restrict__ ei_words) {
    int t = blockIdx.x * blockDim.x + threadIdx.x;
    if (t < NN) g_cnt[t] = 0;
    if (t == 0) g_total = 0;
    if (blockIdx.x == 0 && threadIdx.x < 32) {
        unsigned int nz = 0;
#pragma unroll
        for (int i = 0; i < 4; i++) {
            int s = threadIdx.x * 4 + i;            // 128 samples
            nz |= ei_words[2 * (s * 997 + 1) + 1];  // odd words
        }
        unsigned int any = __ballot_sync(0xffffffffu, nz != 0);
        if (threadIdx.x == 0) g_is64 = (any == 0);
    }
}

// decode edges (int64 or int32) + in-degree histogram + pack int2
__global__ void k_prep_edges(const void* __restrict__ ei) {
    int e = blockIdx.x * blockDim.x + threadIdx.x;
    if (e >= EE) return;
    int r, c;
    if (g_is64) {
        const long long* p = (const long long*)ei;
        r = (int)p[e];
        c = (int)p[EE + e];
    } else {
        const int* p = (const int*)ei;
        r = p[e];
        c = p[EE + e];
    }
    g_edge[e] = make_int2(r, c);
    atomicAdd(&g_cnt[c], 1);
}

// ---- offsets: warp-aggregated atomic bump (bucket order is arbitrary) ------
__global__ void k_offsets() {
    int v = blockIdx.x * blockDim.x + threadIdx.x;
    int lane = threadIdx.x & 31;
    int c = (v < NN) ? g_cnt[v] : 0;
    int incl = c;
#pragma unroll
    for (int d = 1; d < 32; d <<= 1) {
        int u = __shfl_up_sync(0xffffffffu, incl, d);
        if (lane >= d) incl += u;
    }
    int tot = __shfl_sync(0xffffffffu, incl, 31);
    int base = 0;
    if (lane == 31) base = atomicAdd(&g_total, tot);
    base = __shfl_sync(0xffffffffu, base, 31);
    if (v < NN) {
        int off = base + incl - c;   // exclusive within warp
        g_off[v] = off;
        g_cur[v] = off;
        g_dis[v] = rsqrtf(1.0f + (float)c);
    }
}

// fill CSR: for each edge, append its row id to col's bucket
__global__ void k_fill() {
    int e = blockIdx.x * blockDim.x + threadIdx.x;
    if (e >= EE) return;
    int2 rc = g_edge[e];
    int pos = atomicAdd(&g_cur[rc.y], 1);
    g_csr[pos] = rc.x;
}

// ------------- fused GEMM: [N,128] x [128, 64+32] ---------------------------
// 128-row x 96-col block tile, 192 threads, 8x8 register tile per thread.
// layer==0: X = Xin (param). layer==1: X = g_h1 (device-side reference)
// cols 0..63 -> g_sb (scaled by dis); cols 64..95 -> g_cw (+ bc)
__global__ void __launch_bounds__(192) k_gemm(
        const float* __restrict__ Xin, int layer,
        const float* __restrict__ Wb,
        const float* __restrict__ Wc,
        const float* __restrict__ bc) {
    const float* X = (layer == 0) ? Xin : g_h1;
    __shared__ float Xs[128][33];   // row-major, pitch 33
    __shared__ float Ws[32][96];
    int tid = threadIdx.x;
    int tx = tid % 12;         // col group: cols tx*8 .. tx*8+7
    int ty = tid / 12;         // row group: rows ty*8 .. ty*8+7
    int row0 = blockIdx.x * 128;

    float acc[8][8];
#pragma unroll
    for (int i = 0; i < 8; i++)
#pragma unroll
        for (int j = 0; j < 8; j++) acc[i][j] = 0.f;

    for (int kb = 0; kb < 4; kb++) {
        // X tile: 128 rows x 32 k = 1024 float4
        for (int i = tid; i < 1024; i += 192) {
            int rr = i >> 3;
            int qq = i & 7;
            int grow = row0 + rr;
            float4 v = make_float4(0.f, 0.f, 0.f, 0.f);
            if (grow < NN)
                v = *(const float4*)(X + grow * 128 + kb * 32 + qq * 4);
            Xs[rr][qq * 4 + 0] = v.x;
            Xs[rr][qq * 4 + 1] = v.y;
            Xs[rr][qq * 4 + 2] = v.z;
            Xs[rr][qq * 4 + 3] = v.w;
        }
        // W tile: 32 k x 96 cols = 768 float4 (16 from Wb, 8 from Wc per k)
        for (int i = tid; i < 768; i += 192) {
            int kk = i / 24;
            int q  = i % 24;
            int k = kb * 32 + kk;
            float4 v;
            int cc;
            if (q < 16) { v = *(const float4*)(Wb + k * 64 + q * 4); cc = q * 4; }
            else        { v = *(const float4*)(Wc + k * 32 + (q - 16) * 4); cc = 64 + (q - 16) * 4; }
            *(float4*)&Ws[kk][cc] = v;
        }
        __syncthreads();
#pragma unroll
        for (int k = 0; k < 32; k++) {
            float xv[8];
#pragma unroll
            for (int i = 0; i < 8; i++) xv[i] = Xs[ty * 8 + i][k];
            float4 wa = *(const float4*)&Ws[k][tx * 8];
            float4 wb = *(const float4*)&Ws[k][tx * 8 + 4];
            float wv[8] = {wa.x, wa.y, wa.z, wa.w, wb.x, wb.y, wb.z, wb.w};
#pragma unroll
            for (int i = 0; i < 8; i++)
#pragma unroll
                for (int j = 0; j < 8; j++)
                    acc[i][j] += xv[i] * wv[j];
        }
        __syncthreads();
    }

    // epilogue: tx<8 -> sb (x dis), tx>=8 -> cw (+bc); 8 cols per thread
#pragma unroll
    for (int i = 0; i < 8; i++) {
        int grow = row0 + ty * 8 + i;
        if (grow >= NN) continue;
        if (tx < 8) {
            float dv = g_dis[grow];
            float4 s0 = make_float4(dv * acc[i][0], dv * acc[i][1],
                                    dv * acc[i][2], dv * acc[i][3]);
            float4 s1 = make_float4(dv * acc[i][4], dv * acc[i][5],
                                    dv * acc[i][6], dv * acc[i][7]);
            *(float4*)(g_sb + grow * 64 + tx * 8)     = s0;
            *(float4*)(g_sb + grow * 64 + tx * 8 + 4) = s1;
        } else {
            int c0 = (tx - 8) * 8;
            float4 s0 = make_float4(acc[i][0] + bc[c0 + 0], acc[i][1] + bc[c0 + 1],
                                    acc[i][2] + bc[c0 + 2], acc[i][3] + bc[c0 + 3]);
            float4 s1 = make_float4(acc[i][4] + bc[c0 + 4], acc[i][5] + bc[c0 + 5],
                                    acc[i][6] + bc[c0 + 6], acc[i][7] + bc[c0 + 7]);
            *(float4*)(g_cw + grow * 32 + c0)     = s0;
            *(float4*)(g_cw + grow * 32 + c0 + 4) = s1;
        }
    }
}

// ------------- fused gather + combine (+classifier on layer 2) --------------
__global__ void k_aggcomb(const float* __restrict__ bias, int layer,
                          const float* __restrict__ Wcls) {
    __shared__ float sAgg[8][64];
    __shared__ float sCw[8][32];
    int warp = threadIdx.x >> 5;
    int lane = threadIdx.x & 31;
    int v = blockIdx.x * 8 + warp;      // 6250 * 8 == 50000 exactly

    int s  = g_off[v];
    int e2 = s + g_cnt[v];
    float acc0 = g_sb[v * 64 + lane];        // self-loop term
    float acc1 = g_sb[v * 64 + 32 + lane];

    int j = s;
    for (; j + 3 < e2; j += 4) {             // unroll 4 -> MLP 8
        int r0 = g_csr[j];
        int r1 = g_csr[j + 1];
        int r2 = g_csr[j + 2];
        int r3 = g_csr[j + 3];
        float a0 = g_sb[r0 * 64 + lane];
        float b0 = g_sb[r0 * 64 + 32 + lane];
        float a1 = g_sb[r1 * 64 + lane];
        float b1 = g_sb[r1 * 64 + 32 + lane];
        float a2 = g_sb[r2 * 64 + lane];
        float b2 = g_sb[r2 * 64 + 32 + lane];
        float a3 = g_sb[r3 * 64 + lane];
        float b3 = g_sb[r3 * 64 + 32 + lane];
        acc0 += (a0 + a1) + (a2 + a3);
        acc1 += (b0 + b1) + (b2 + b3);
    }
    for (; j < e2; j++) {
        int r0 = g_csr[j];
        acc0 += g_sb[r0 * 64 + lane];
        acc1 += g_sb[r0 * 64 + 32 + lane];
    }

    float dv = g_dis[v];
    sAgg[warp][lane]      = dv * acc0;
    sAgg[warp][lane + 32] = dv * acc1;
    sCw[warp][lane] = g_cw[v * 32 + lane];
    __syncwarp();

    if (layer == 0) {
#pragma unroll
        for (int t = 0; t < 4; t++) {
            int o  = lane + 32 * t;              // output index 0..127
            int hh = o >> 4, f = o & 15;
            float sum = bias[o];
#pragma unroll
            for (int b = 0; b < 4; b++)
                sum += sCw[warp][hh * 4 + b] * sAgg[warp][b * 16 + f];
            g_h1[v * 128 + o] = fmaxf(sum, 0.f);
        }
    } else {
        float a00 = 0.f, a01 = 0.f, a10 = 0.f, a11 = 0.f;
#pragma unroll
        for (int t = 0; t < 4; t++) {
            int o  = lane + 32 * t;
            int hh = o >> 4, f = o & 15;
            float sum = bias[o];
#pragma unroll
            for (int b = 0; b < 4; b++)
                sum += sCw[warp][hh * 4 + b] * sAgg[warp][b * 16 + f];
            a00 += sum * Wcls[o * 2 + 0];
            a01 += sum * Wcls[o * 2 + 1];
            a10 += sum * Wcls[(128 + o) * 2 + 0];
            a11 += sum * Wcls[(128 + o) * 2 + 1];
        }
#pragma unroll
        for (int o = 16; o; o >>= 1) {
            a00 += __shfl_xor_sync(0xffffffffu, a00, o);
            a01 += __shfl_xor_sync(0xffffffffu, a01, o);
            a10 += __shfl_xor_sync(0xffffffffu, a10, o);
            a11 += __shfl_xor_sync(0xffffffffu, a11, o);
        }
        if (lane == 0) {
            g_pre0[v] = make_float2(a00, a01);
            g_pre1[v] = make_float2(a10, a11);
        }
    }
}

// ------------- edge output: out[e] = pre0[src] + pre1[dst] + bcls -----------
__global__ void k_edgeout(const float* __restrict__ bcls,
                          float2* __restrict__ out) {
    int e = blockIdx.x * blockDim.x + threadIdx.x;
    if (e >= EE) return;
    int2 rc = g_edge[e];
    float2 p0 = g_pre0[rc.x];
    float2 p1 = g_pre1[rc.y];
    out[e] = make_float2(p0.x + p1.x + bcls[0], p0.y + p1.y + bcls[1]);
}

// ------------- launch: resolve inputs BY SIZE (order-agnostic) --------------
extern "C" void kernel_launch(void* const* d_in, const int* in_sizes, int n_in,
                              void* d_out, int out_size) {
    const float *x = 0, *Wb1 = 0, *Wc1 = 0, *bc1 = 0, *b1 = 0;
    const float *Wb2 = 0, *Wc2 = 0, *bc2 = 0, *b2 = 0, *Wcls = 0, *bcls = 0;
    const void* ei = 0;

    for (int i = 0; i < n_in; i++) {
        const float* p = (const float*)d_in[i];
        switch (in_sizes[i]) {
            case 6400000: x = p; break;                       // [50000,128]
            case 1600000: ei = d_in[i]; break;                // [2,800000]
            case 8192:    if (!Wb1) Wb1 = p; else Wb2 = p; break;
            case 4096:    if (!Wc1) Wc1 = p; else Wc2 = p; break;
            case 512:     Wcls = p; break;
            case 128:     if (!b1) b1 = p; else b2 = p; break;
            case 32:      if (!bc1) bc1 = p; else bc2 = p; break;
            case 2:       bcls = p; break;
            default: break;
        }
    }
    if (!x && n_in >= 12) {   // positional fallback (canonical dict order)
        x = (const float*)d_in[0]; ei = d_in[1];
        Wb1 = (const float*)d_in[2]; Wc1 = (const float*)d_in[3];
        bc1 = (const float*)d_in[4]; b1 = (const float*)d_in[5];
        Wb2 = (const float*)d_in[6]; Wc2 = (const float*)d_in[7];
        bc2 = (const float*)d_in[8]; b2 = (const float*)d_in[9];
        Wcls = (const float*)d_in[10]; bcls = (const float*)d_in[11];
    }
    float2* out = (float2*)d_out;

    // ---- graph prep: CSR by col (4 launches) ----
    k_init<<<NBLK, 256>>>((const unsigned int*)ei);
    k_prep_edges<<<(EE + 255) / 256, 256>>>(ei);
    k_offsets<<<NBLK, 256>>>();
    k_fill<<<(EE + 255) / 256, 256>>>();

    // ---- layer 1 ----
    k_gemm<<<(NN + 127) / 128, 192>>>(x, 0, Wb1, Wc1, bc1);
    k_aggcomb<<<NN / 8, 256>>>(b1, 0, Wcls);

    // ---- layer 2 (classifier precompute fused in) ----
    k_gemm<<<(NN + 127) / 128, 192>>>(x, 1, Wb2, Wc2, bc2);
    k_aggcomb<<<NN / 8, 256>>>(b2, 1, Wcls);

    // ---- edge output ----
    k_edgeout<<<(EE + 255) / 256, 256>>>(bcls, out);
}